// round 14
// baseline (speedup 1.0000x reference)
#include <cuda_runtime.h>

#define NQ  8
#define DIM 256
#define SQ2 0.70710678118654752f

__device__ __align__(16) float2 g_psi[DIM];

__device__ __constant__ unsigned char PI_[28] =
    {0,0,0,0,0,0,0,1,1,1,1,1,1,2,2,2,2,2,3,3,3,3,4,4,4,5,5,6};
__device__ __constant__ unsigned char PJ_[28] =
    {1,2,3,4,5,6,7,2,3,4,5,6,7,3,4,5,6,7,4,5,6,7,5,6,7,6,7,7};

__device__ __forceinline__ float2 cmul(float2 a, float2 b) {
    return make_float2(a.x * b.x - a.y * b.y, a.x * b.y + a.y * b.x);
}
__device__ __forceinline__ float2 cmad(float2 acc, float2 a, float2 b) {
    return make_float2(acc.x + a.x * b.x - a.y * b.y,
                       acc.y + a.x * b.y + a.y * b.x);
}
__device__ __forceinline__ float2 shfl2(float2 v, int m) {
    return make_float2(__shfl_xor_sync(0xffffffffu, v.x, m),
                       __shfl_xor_sync(0xffffffffu, v.y, m));
}
// tree-form 4-term complex dot: M[c0]*a0 + M[c1]*a1 + M[c2]*a2 + M[c3]*a3
__device__ __forceinline__ float2 dot4(const float2* M, int c0, int c1, int c2, int c3,
                                       float2 a0, float2 a1, float2 a2, float2 a3) {
    float2 t0 = cmad(cmul(M[c0], a0), M[c1], a1);
    float2 t1 = cmad(cmul(M[c2], a2), M[c3], a3);
    return make_float2(t0.x + t1.x, t0.y + t1.y);
}

// ---------------------------------------------------------------------------
// Every block runs the IDENTICAL evolution, then writes its own 4-row output
// slice. State is register-carried; intra-warp steps gather via shfl.
// ---------------------------------------------------------------------------
__global__ void __launch_bounds__(256, 1)
fused_kernel(const float* __restrict__ x,
             const float* __restrict__ w,
             const float* __restrict__ cplg,
             float4* __restrict__ out,
             int mode) {           // 0: write slice; 1: publish g_psi only
    const int tid = threadIdx.x;

    __shared__ float2 sbuf[DIM];
    __shared__ float2 pairM[28][16];
    __shared__ float2 u2s[4][16];
    __shared__ float2 u1s[8][4];
    __shared__ float2 sD[DIM];
    __shared__ float  sw[210];
    __shared__ float  scpl[64];
    __shared__ float  red[8];
    __shared__ int    actL[28];
    __shared__ int    actN_sh;
    __shared__ unsigned amask_sh;

    const int lane = tid & 31;
    const int wid  = tid >> 5;

    if (tid < 210) sw[tid]   = w[tid];
    if (tid < 64)  scpl[tid] = cplg[tid];
    const float xv = x[tid];
    float ssum = xv * xv;
#pragma unroll
    for (int o = 16; o; o >>= 1) ssum += __shfl_xor_sync(0xffffffffu, ssum, o);
    if (lane == 0) red[wid] = ssum;
    __syncthreads();                               // sync0

    // ---------------- phase 1 ----------------
    const float inv = rsqrtf(red[0] + red[1] + red[2] + red[3] +
                             red[4] + red[5] + red[6] + red[7]);
    float2 r = make_float2(xv * inv, 0.f);
    sbuf[tid] = r;

    {   // per-thread ising diagonal phase
        float th = 0.f;
#pragma unroll
        for (int p = 0; p < 28; p++) {
            const int i = PI_[p], j = PJ_[p];
            const float phi = scpl[i * 8 + j];
            const int b = ((tid >> (7 - i)) ^ (tid >> (7 - j))) & 1;
            th += b ? -0.5f * phi : 0.5f * phi;
        }
        float s, c;
        __sincosf(th, &s, &c);
        sD[tid] = make_float2(c, -s);
    }

    if (wid == 0) {
        float mn = fminf(scpl[lane], scpl[lane + 32]);
        float mx = fmaxf(scpl[lane], scpl[lane + 32]);
#pragma unroll
        for (int o = 16; o; o >>= 1) {
            mn = fminf(mn, __shfl_xor_sync(0xffffffffu, mn, o));
            mx = fmaxf(mx, __shfl_xor_sync(0xffffffffu, mx, o));
        }
        const float range = mx - mn;
        bool bit = false;
        if (lane < 28)
            bit = (scpl[PI_[lane] * 8 + PJ_[lane]] - mn) / range > 0.5f;
        const unsigned am = __ballot_sync(0xffffffffu, bit);
        if (lane == 0) amask_sh = am;
    } else if (tid >= 128 && tid < 136) {
        // u' = H * Rz*Ry*Rx for qubit q
        const int q = tid - 128;
        float sx, cx, sy, cy, sz, cz;
        __sincosf(0.5f * sw[q],      &sx, &cx);
        __sincosf(0.5f * sw[q + 8],  &sy, &cy);
        __sincosf(0.5f * sw[q + 16], &sz, &cz);
        const float2 A00 = make_float2(cy * cx,  sy * sx);
        const float2 A01 = make_float2(-sy * cx, -cy * sx);
        const float2 A10 = make_float2( sy * cx, -cy * sx);
        const float2 A11 = make_float2(cy * cx, -sy * sx);
        const float2 ez  = make_float2(cz, -sz);
        const float2 ezc = make_float2(cz,  sz);
        const float2 u00 = cmul(ez,  A00);
        const float2 u01 = cmul(ez,  A01);
        const float2 u10 = cmul(ezc, A10);
        const float2 u11 = cmul(ezc, A11);
        u1s[q][0] = make_float2(SQ2 * (u00.x + u10.x), SQ2 * (u00.y + u10.y));
        u1s[q][1] = make_float2(SQ2 * (u01.x + u11.x), SQ2 * (u01.y + u11.y));
        u1s[q][2] = make_float2(SQ2 * (u00.x - u10.x), SQ2 * (u00.y - u10.y));
        u1s[q][3] = make_float2(SQ2 * (u01.x - u11.x), SQ2 * (u01.y - u11.y));
    }
    __syncthreads();                               // sync1
    const unsigned amask = amask_sh;

    // ---------------- phase 2 ----------------
    if (tid < 112) {
        const int p   = tid >> 2;
        const int col = tid & 3;
        const int widx = 3 * NQ + 6 * __popc(amask & ((1u << p) - 1u));

        float2 v0 = make_float2(col == 0 ? 1.f : 0.f, 0.f);
        float2 v1 = make_float2(col == 1 ? 1.f : 0.f, 0.f);
        float2 v2 = make_float2(col == 2 ? 1.f : 0.f, 0.f);
        float2 v3 = make_float2(col == 3 ? 1.f : 0.f, 0.f);

#define PHASE_I(er, ei) { const float2 e = make_float2(er, ei), ec = make_float2(er, -(ei)); \
        v0 = cmul(v0, e); v1 = cmul(v1, e); v2 = cmul(v2, ec); v3 = cmul(v3, ec); }
#define PHASE_J(er, ei) { const float2 e = make_float2(er, ei), ec = make_float2(er, -(ei)); \
        v0 = cmul(v0, e); v1 = cmul(v1, ec); v2 = cmul(v2, e); v3 = cmul(v3, ec); }
#define RY_J(c, s) { float2 t; \
        t  = make_float2((c)*v0.x - (s)*v1.x, (c)*v0.y - (s)*v1.y); \
        v1 = make_float2((s)*v0.x + (c)*v1.x, (s)*v0.y + (c)*v1.y); v0 = t; \
        t  = make_float2((c)*v2.x - (s)*v3.x, (c)*v2.y - (s)*v3.y); \
        v3 = make_float2((s)*v2.x + (c)*v3.x, (s)*v2.y + (c)*v3.y); v2 = t; }
#define SWAP13 { const float2 t = v1; v1 = v3; v3 = t; }
#define SWAP23 { const float2 t = v2; v2 = v3; v3 = t; }

        float s0, c0, s1, c1, s2, c2, s3, c3, s4, c4, s5, c5;
        __sincosf(0.5f * sw[widx + 0], &s0, &c0);
        __sincosf(0.5f * sw[widx + 1], &s1, &c1);
        __sincosf(0.5f * sw[widx + 2], &s2, &c2);
        __sincosf(0.5f * sw[widx + 3], &s3, &c3);
        __sincosf(0.5f * sw[widx + 4], &s4, &c4);
        __sincosf(0.5f * sw[widx + 5], &s5, &c5);

        PHASE_J(SQ2,  SQ2);
        SWAP13;
        PHASE_I(c0, -s0);
        RY_J(c1, s1);
        SWAP23;
        RY_J(c2, s2);
        SWAP13;
        PHASE_I(SQ2, -SQ2);
        PHASE_J(SQ2,  SQ2);
        SWAP13;
        PHASE_I(c3, -s3);
        RY_J(c4, s4);
        SWAP23;
        RY_J(c5, s5);

        pairM[p][0 * 4 + col] = v0;
        pairM[p][1 * 4 + col] = v1;
        pairM[p][2 * 4 + col] = v2;
        pairM[p][3 * 4 + col] = v3;
#undef PHASE_I
#undef PHASE_J
#undef RY_J
#undef SWAP13
#undef SWAP23
    } else if (tid < 176) {
        const int t   = tid - 112;
        const int g   = t >> 4;
        const int row = (t >> 2) & 3;
        const int col = t & 3;
        const float2 ea = u1s[2 * g][(row >> 1) * 2 + (col >> 1)];
        const float2 eb = u1s[2 * g + 1][(row & 1) * 2 + (col & 1)];
        u2s[g][row * 4 + col] = cmul(ea, eb);
    } else if (tid == 192) {
        int n = 0;
#pragma unroll
        for (int p = 0; p < 28; p++) {
            if ((amask >> p) & 1u) {
                const int mi = 1 << (7 - PI_[p]);
                const int mj = 1 << (7 - PJ_[p]);
                int e = p | (mi << 8) | (mj << 16);
                if ((mi | mj) < 32) e |= 1 << 24;   // intra-warp step
                actL[n++] = e;
            }
        }
        actN_sh = n;
    }
    __syncthreads();                               // sync2: chain start
    const int actN = actN_sh;

    // ================= chain (register-carried state) =================

    // step 1: 1q pair (bits 7,6), cross — sbuf current, r == sbuf[tid]
    {
        const int ma = 128, mb = 64;
        const int row = (((tid >> 7) & 1) << 1) | ((tid >> 6) & 1);
        const float2* M = &u2s[0][row << 2];
        r = dot4(M, row, row ^ 1, row ^ 2, row ^ 3,
                 r, sbuf[tid ^ mb], sbuf[tid ^ ma], sbuf[tid ^ ma ^ mb]);
    }
    // step 2: 1q pair (bits 5,4), cross
    {
        sbuf[tid] = r; __syncthreads();
        const int ma = 32, mb = 16;
        const int row = (((tid >> 5) & 1) << 1) | ((tid >> 4) & 1);
        const float2* M = &u2s[1][row << 2];
        r = dot4(M, row, row ^ 1, row ^ 2, row ^ 3,
                 r, sbuf[tid ^ mb], sbuf[tid ^ ma], sbuf[tid ^ ma ^ mb]);
    }
    // step 3: 1q pair (bits 3,2), intra — shfl
    {
        const int row = (((tid >> 3) & 1) << 1) | ((tid >> 2) & 1);
        const float2* M = &u2s[2][row << 2];
        r = dot4(M, row, row ^ 1, row ^ 2, row ^ 3,
                 r, shfl2(r, 4), shfl2(r, 8), shfl2(r, 12));
    }
    // step 4: 1q pair (bits 1,0), intra + ising diagonal
    {
        const int row = tid & 3;
        const float2* M = &u2s[3][row << 2];
        r = dot4(M, row, row ^ 1, row ^ 2, row ^ 3,
                 r, shfl2(r, 1), shfl2(r, 2), shfl2(r, 3));
        r = cmul(sD[tid], r);
    }
    // steps 5,6: HH (3,2) then (1,0) — intra, partner form
#pragma unroll
    for (int g = 0; g < 2; g++) {
        const int ma = g ? 2 : 8, mb = g ? 1 : 4;
        const float sa = (tid & ma) ? -1.f : 1.f;
        const float sb = (tid & mb) ? -1.f : 1.f;
        const float2 p1 = shfl2(r, mb);
        const float2 p2 = shfl2(r, ma);
        const float2 p3 = shfl2(r, ma | mb);
        float2 t0 = make_float2(sa * (sb * r.x + p1.x), sa * (sb * r.y + p1.y));
        float2 t1 = make_float2(sb * p2.x + p3.x,       sb * p2.y + p3.y);
        r = make_float2(0.5f * (t0.x + t1.x), 0.5f * (t0.y + t1.y));
    }
    // steps 7,8: HH (7,6) then (5,4) — cross, partner form
#pragma unroll
    for (int g = 0; g < 2; g++) {
        sbuf[tid] = r; __syncthreads();
        const int ma = g ? 32 : 128, mb = g ? 16 : 64;
        const float sa = (tid & ma) ? -1.f : 1.f;
        const float sb = (tid & mb) ? -1.f : 1.f;
        const float2 p1 = sbuf[tid ^ mb];
        const float2 p2 = sbuf[tid ^ ma];
        const float2 p3 = sbuf[tid ^ ma ^ mb];
        float2 t0 = make_float2(sa * (sb * r.x + p1.x), sa * (sb * r.y + p1.y));
        float2 t1 = make_float2(sb * p2.x + p3.x,       sb * p2.y + p3.y);
        r = make_float2(0.5f * (t0.x + t1.x), 0.5f * (t0.y + t1.y));
    }

    // conv+pool steps (uniform per-step branch)
#pragma unroll 1
    for (int a = 0; a < actN; a++) {
        const int packed = actL[a];
        const int p  = packed & 255;
        const int mi = (packed >> 8) & 255;
        const int mj = (packed >> 16) & 255;
        const int row = ((tid & mi) ? 2 : 0) | ((tid & mj) ? 1 : 0);
        const float2* M = &pairM[p][row << 2];
        if (packed & (1 << 24)) {      // intra-warp: shfl partners
            r = dot4(M, row, row ^ 1, row ^ 2, row ^ 3,
                     r, shfl2(r, mj), shfl2(r, mi), shfl2(r, mi | mj));
        } else {                       // cross-warp: smem partners
            sbuf[tid] = r; __syncthreads();
            r = dot4(M, row, row ^ 1, row ^ 2, row ^ 3,
                     r, sbuf[tid ^ mj], sbuf[tid ^ mi], sbuf[tid ^ mi ^ mj]);
        }
    }

    sbuf[tid] = r;
    __syncthreads();                               // epilogue reads all amps

    if (mode == 1) {
        g_psi[tid] = r;
        return;
    }

    // ---- write this block's 4-row output slice (real part) ----
    const int rr = (blockIdx.x << 2) | (tid >> 6);
    const int q  = tid & 63;
    const float2 a  = sbuf[rr];
    const float2 b0 = sbuf[(q << 2)];
    const float2 b1 = sbuf[(q << 2) + 1];
    const float2 b2 = sbuf[(q << 2) + 2];
    const float2 b3 = sbuf[(q << 2) + 3];
    float4 o;
    o.x = a.x * b0.x + a.y * b0.y;
    o.y = a.x * b1.x + a.y * b1.y;
    o.z = a.x * b2.x + a.y * b2.y;
    o.w = a.x * b3.x + a.y * b3.y;
    out[(rr << 6) + q] = o;
}

// fallback for unexpected out_size (planar [Re|Im])
__global__ void __launch_bounds__(256)
outer_planar_kernel(float* __restrict__ out) {
    const int r = blockIdx.x;
    const int c = threadIdx.x;
    const float2 a = g_psi[r];
    const float2 b = g_psi[c];
    out[r * DIM + c]             = a.x * b.x + a.y * b.y;
    out[DIM * DIM + r * DIM + c] = a.y * b.x - a.x * b.y;
}

extern "C" void kernel_launch(void* const* d_in, const int* in_sizes, int n_in,
                              void* d_out, int out_size) {
    const float* x   = nullptr;
    const float* w   = nullptr;
    const float* cpl = nullptr;
    for (int i = 0; i < n_in; i++) {
        if      (in_sizes[i] == 256) x   = (const float*)d_in[i];
        else if (in_sizes[i] == 210) w   = (const float*)d_in[i];
        else if (in_sizes[i] == 64)  cpl = (const float*)d_in[i];
    }

    if (out_size == DIM * DIM) {
        fused_kernel<<<64, 256>>>(x, w, cpl, (float4*)d_out, 0);
    } else {
        fused_kernel<<<1, 256>>>(x, w, cpl, (float4*)d_out, 1);
        outer_planar_kernel<<<DIM, DIM>>>((float*)d_out);
    }
}

// round 15
// speedup vs baseline: 1.0341x; 1.0341x over previous
#include <cuda_runtime.h>

#define NQ  8
#define DIM 256
#define SQ2 0.70710678118654752f

__device__ __align__(16) float2 g_psi[DIM];

__device__ __constant__ unsigned char PI_[28] =
    {0,0,0,0,0,0,0,1,1,1,1,1,1,2,2,2,2,2,3,3,3,3,4,4,4,5,5,6};
__device__ __constant__ unsigned char PJ_[28] =
    {1,2,3,4,5,6,7,2,3,4,5,6,7,3,4,5,6,7,4,5,6,7,5,6,7,6,7,7};

__device__ __forceinline__ float2 cmul(float2 a, float2 b) {
    return make_float2(a.x * b.x - a.y * b.y, a.x * b.y + a.y * b.x);
}
__device__ __forceinline__ float2 cmad(float2 acc, float2 a, float2 b) {
    return make_float2(acc.x + a.x * b.x - a.y * b.y,
                       acc.y + a.x * b.y + a.y * b.x);
}
__device__ __forceinline__ float2 shfl2(float2 v, int m) {
    return make_float2(__shfl_xor_sync(0xffffffffu, v.x, m),
                       __shfl_xor_sync(0xffffffffu, v.y, m));
}
// tree-form 4-term complex dot: M[c0]*a0 + M[c1]*a1 + M[c2]*a2 + M[c3]*a3
__device__ __forceinline__ float2 dot4(const float2* M, int c0, int c1, int c2, int c3,
                                       float2 a0, float2 a1, float2 a2, float2 a3) {
    float2 t0 = cmad(cmul(M[c0], a0), M[c1], a1);
    float2 t1 = cmad(cmul(M[c2], a2), M[c3], a3);
    return make_float2(t0.x + t1.x, t0.y + t1.y);
}

// ---------------------------------------------------------------------------
// Every block runs the IDENTICAL evolution, then writes its own 4-row output
// slice. State is register-carried; intra-warp steps gather via shfl.
// ---------------------------------------------------------------------------
__global__ void __launch_bounds__(256, 1)
fused_kernel(const float* __restrict__ x,
             const float* __restrict__ w,
             const float* __restrict__ cplg,
             float4* __restrict__ out,
             int mode) {           // 0: write slice; 1: publish g_psi only
    const int tid = threadIdx.x;

    __shared__ float2 sbuf[DIM];
    __shared__ float2 pairM[28][16];
    __shared__ float2 u2s[4][16];
    __shared__ float2 u1s[8][4];
    __shared__ float2 sD[DIM];
    __shared__ float  sw[210];
    __shared__ float  scpl[64];
    __shared__ float  red[8];
    __shared__ int    actL[28];
    __shared__ int    actN_sh;
    __shared__ unsigned amask_sh;

    const int lane = tid & 31;
    const int wid  = tid >> 5;

    if (tid < 210) sw[tid]   = w[tid];
    if (tid < 64)  scpl[tid] = cplg[tid];
    const float xv = x[tid];
    float ssum = xv * xv;
#pragma unroll
    for (int o = 16; o; o >>= 1) ssum += __shfl_xor_sync(0xffffffffu, ssum, o);
    if (lane == 0) red[wid] = ssum;
    __syncthreads();                               // sync0

    // ---------------- phase 1 ----------------
    const float inv = rsqrtf(red[0] + red[1] + red[2] + red[3] +
                             red[4] + red[5] + red[6] + red[7]);
    float2 r = make_float2(xv * inv, 0.f);
    sbuf[tid] = r;

    {   // per-thread ising diagonal phase
        float th = 0.f;
#pragma unroll
        for (int p = 0; p < 28; p++) {
            const int i = PI_[p], j = PJ_[p];
            const float phi = scpl[i * 8 + j];
            const int b = ((tid >> (7 - i)) ^ (tid >> (7 - j))) & 1;
            th += b ? -0.5f * phi : 0.5f * phi;
        }
        float s, c;
        __sincosf(th, &s, &c);
        sD[tid] = make_float2(c, -s);
    }

    if (wid == 0) {
        float mn = fminf(scpl[lane], scpl[lane + 32]);
        float mx = fmaxf(scpl[lane], scpl[lane + 32]);
#pragma unroll
        for (int o = 16; o; o >>= 1) {
            mn = fminf(mn, __shfl_xor_sync(0xffffffffu, mn, o));
            mx = fmaxf(mx, __shfl_xor_sync(0xffffffffu, mx, o));
        }
        const float range = mx - mn;
        bool bit = false;
        if (lane < 28)
            bit = (scpl[PI_[lane] * 8 + PJ_[lane]] - mn) / range > 0.5f;
        const unsigned am = __ballot_sync(0xffffffffu, bit);
        if (lane == 0) amask_sh = am;
    } else if (tid >= 128 && tid < 136) {
        // u' = H * Rz*Ry*Rx for qubit q
        const int q = tid - 128;
        float sx, cx, sy, cy, sz, cz;
        __sincosf(0.5f * sw[q],      &sx, &cx);
        __sincosf(0.5f * sw[q + 8],  &sy, &cy);
        __sincosf(0.5f * sw[q + 16], &sz, &cz);
        const float2 A00 = make_float2(cy * cx,  sy * sx);
        const float2 A01 = make_float2(-sy * cx, -cy * sx);
        const float2 A10 = make_float2( sy * cx, -cy * sx);
        const float2 A11 = make_float2(cy * cx, -sy * sx);
        const float2 ez  = make_float2(cz, -sz);
        const float2 ezc = make_float2(cz,  sz);
        const float2 u00 = cmul(ez,  A00);
        const float2 u01 = cmul(ez,  A01);
        const float2 u10 = cmul(ezc, A10);
        const float2 u11 = cmul(ezc, A11);
        u1s[q][0] = make_float2(SQ2 * (u00.x + u10.x), SQ2 * (u00.y + u10.y));
        u1s[q][1] = make_float2(SQ2 * (u01.x + u11.x), SQ2 * (u01.y + u11.y));
        u1s[q][2] = make_float2(SQ2 * (u00.x - u10.x), SQ2 * (u00.y - u10.y));
        u1s[q][3] = make_float2(SQ2 * (u01.x - u11.x), SQ2 * (u01.y - u11.y));
    }
    __syncthreads();                               // sync1
    const unsigned amask = amask_sh;

    // ---------------- phase 2 ----------------
    if (tid < 112) {
        const int p   = tid >> 2;
        const int col = tid & 3;
        const int widx = 3 * NQ + 6 * __popc(amask & ((1u << p) - 1u));

        float2 v0 = make_float2(col == 0 ? 1.f : 0.f, 0.f);
        float2 v1 = make_float2(col == 1 ? 1.f : 0.f, 0.f);
        float2 v2 = make_float2(col == 2 ? 1.f : 0.f, 0.f);
        float2 v3 = make_float2(col == 3 ? 1.f : 0.f, 0.f);

#define PHASE_I(er, ei) { const float2 e = make_float2(er, ei), ec = make_float2(er, -(ei)); \
        v0 = cmul(v0, e); v1 = cmul(v1, e); v2 = cmul(v2, ec); v3 = cmul(v3, ec); }
#define PHASE_J(er, ei) { const float2 e = make_float2(er, ei), ec = make_float2(er, -(ei)); \
        v0 = cmul(v0, e); v1 = cmul(v1, ec); v2 = cmul(v2, e); v3 = cmul(v3, ec); }
#define RY_J(c, s) { float2 t; \
        t  = make_float2((c)*v0.x - (s)*v1.x, (c)*v0.y - (s)*v1.y); \
        v1 = make_float2((s)*v0.x + (c)*v1.x, (s)*v0.y + (c)*v1.y); v0 = t; \
        t  = make_float2((c)*v2.x - (s)*v3.x, (c)*v2.y - (s)*v3.y); \
        v3 = make_float2((s)*v2.x + (c)*v3.x, (s)*v2.y + (c)*v3.y); v2 = t; }
#define SWAP13 { const float2 t = v1; v1 = v3; v3 = t; }
#define SWAP23 { const float2 t = v2; v2 = v3; v3 = t; }

        float s0, c0, s1, c1, s2, c2, s3, c3, s4, c4, s5, c5;
        __sincosf(0.5f * sw[widx + 0], &s0, &c0);
        __sincosf(0.5f * sw[widx + 1], &s1, &c1);
        __sincosf(0.5f * sw[widx + 2], &s2, &c2);
        __sincosf(0.5f * sw[widx + 3], &s3, &c3);
        __sincosf(0.5f * sw[widx + 4], &s4, &c4);
        __sincosf(0.5f * sw[widx + 5], &s5, &c5);

        PHASE_J(SQ2,  SQ2);
        SWAP13;
        PHASE_I(c0, -s0);
        RY_J(c1, s1);
        SWAP23;
        RY_J(c2, s2);
        SWAP13;
        PHASE_I(SQ2, -SQ2);
        PHASE_J(SQ2,  SQ2);
        SWAP13;
        PHASE_I(c3, -s3);
        RY_J(c4, s4);
        SWAP23;
        RY_J(c5, s5);

        pairM[p][0 * 4 + col] = v0;
        pairM[p][1 * 4 + col] = v1;
        pairM[p][2 * 4 + col] = v2;
        pairM[p][3 * 4 + col] = v3;
#undef PHASE_I
#undef PHASE_J
#undef RY_J
#undef SWAP13
#undef SWAP23
    } else if (tid < 176) {
        const int t   = tid - 112;
        const int g   = t >> 4;
        const int row = (t >> 2) & 3;
        const int col = t & 3;
        const float2 ea = u1s[2 * g][(row >> 1) * 2 + (col >> 1)];
        const float2 eb = u1s[2 * g + 1][(row & 1) * 2 + (col & 1)];
        u2s[g][row * 4 + col] = cmul(ea, eb);
    } else if (tid == 192) {
        int n = 0;
#pragma unroll
        for (int p = 0; p < 28; p++) {
            if ((amask >> p) & 1u) {
                const int mi = 1 << (7 - PI_[p]);
                const int mj = 1 << (7 - PJ_[p]);
                int e = p | (mi << 8) | (mj << 16);
                if ((mi | mj) < 32) e |= 1 << 24;   // intra-warp step
                actL[n++] = e;
            }
        }
        actN_sh = n;
    }
    __syncthreads();                               // sync2: chain start
    const int actN = actN_sh;

    // ================= chain (register-carried state) =================

    // step 1: 1q pair (bits 7,6), cross — sbuf current, r == sbuf[tid]
    {
        const int ma = 128, mb = 64;
        const int row = (((tid >> 7) & 1) << 1) | ((tid >> 6) & 1);
        const float2* M = &u2s[0][row << 2];
        r = dot4(M, row, row ^ 1, row ^ 2, row ^ 3,
                 r, sbuf[tid ^ mb], sbuf[tid ^ ma], sbuf[tid ^ ma ^ mb]);
    }
    // step 2: 1q pair (bits 5,4), cross
    {
        sbuf[tid] = r; __syncthreads();
        const int ma = 32, mb = 16;
        const int row = (((tid >> 5) & 1) << 1) | ((tid >> 4) & 1);
        const float2* M = &u2s[1][row << 2];
        r = dot4(M, row, row ^ 1, row ^ 2, row ^ 3,
                 r, sbuf[tid ^ mb], sbuf[tid ^ ma], sbuf[tid ^ ma ^ mb]);
    }
    // step 3: 1q pair (bits 3,2), intra — shfl
    {
        const int row = (((tid >> 3) & 1) << 1) | ((tid >> 2) & 1);
        const float2* M = &u2s[2][row << 2];
        r = dot4(M, row, row ^ 1, row ^ 2, row ^ 3,
                 r, shfl2(r, 4), shfl2(r, 8), shfl2(r, 12));
    }
    // step 4: 1q pair (bits 1,0), intra + ising diagonal
    {
        const int row = tid & 3;
        const float2* M = &u2s[3][row << 2];
        r = dot4(M, row, row ^ 1, row ^ 2, row ^ 3,
                 r, shfl2(r, 1), shfl2(r, 2), shfl2(r, 3));
        r = cmul(sD[tid], r);
    }
    // steps 5,6: HH (3,2) then (1,0) — intra, partner form
#pragma unroll
    for (int g = 0; g < 2; g++) {
        const int ma = g ? 2 : 8, mb = g ? 1 : 4;
        const float sa = (tid & ma) ? -1.f : 1.f;
        const float sb = (tid & mb) ? -1.f : 1.f;
        const float2 p1 = shfl2(r, mb);
        const float2 p2 = shfl2(r, ma);
        const float2 p3 = shfl2(r, ma | mb);
        float2 t0 = make_float2(sa * (sb * r.x + p1.x), sa * (sb * r.y + p1.y));
        float2 t1 = make_float2(sb * p2.x + p3.x,       sb * p2.y + p3.y);
        r = make_float2(0.5f * (t0.x + t1.x), 0.5f * (t0.y + t1.y));
    }
    // steps 7,8: HH (7,6) then (5,4) — cross, partner form
#pragma unroll
    for (int g = 0; g < 2; g++) {
        sbuf[tid] = r; __syncthreads();
        const int ma = g ? 32 : 128, mb = g ? 16 : 64;
        const float sa = (tid & ma) ? -1.f : 1.f;
        const float sb = (tid & mb) ? -1.f : 1.f;
        const float2 p1 = sbuf[tid ^ mb];
        const float2 p2 = sbuf[tid ^ ma];
        const float2 p3 = sbuf[tid ^ ma ^ mb];
        float2 t0 = make_float2(sa * (sb * r.x + p1.x), sa * (sb * r.y + p1.y));
        float2 t1 = make_float2(sb * p2.x + p3.x,       sb * p2.y + p3.y);
        r = make_float2(0.5f * (t0.x + t1.x), 0.5f * (t0.y + t1.y));
    }

    // conv+pool steps (uniform per-step branch)
#pragma unroll 1
    for (int a = 0; a < actN; a++) {
        const int packed = actL[a];
        const int p  = packed & 255;
        const int mi = (packed >> 8) & 255;
        const int mj = (packed >> 16) & 255;
        const int row = ((tid & mi) ? 2 : 0) | ((tid & mj) ? 1 : 0);
        const float2* M = &pairM[p][row << 2];
        if (packed & (1 << 24)) {      // intra-warp: shfl partners
            r = dot4(M, row, row ^ 1, row ^ 2, row ^ 3,
                     r, shfl2(r, mj), shfl2(r, mi), shfl2(r, mi | mj));
        } else {                       // cross-warp: smem partners
            sbuf[tid] = r; __syncthreads();
            r = dot4(M, row, row ^ 1, row ^ 2, row ^ 3,
                     r, sbuf[tid ^ mj], sbuf[tid ^ mi], sbuf[tid ^ mi ^ mj]);
        }
    }

    sbuf[tid] = r;
    __syncthreads();                               // epilogue reads all amps

    if (mode == 1) {
        g_psi[tid] = r;
        return;
    }

    // ---- write this block's 4-row output slice (real part) ----
    const int rr = (blockIdx.x << 2) | (tid >> 6);
    const int q  = tid & 63;
    const float2 a  = sbuf[rr];
    const float2 b0 = sbuf[(q << 2)];
    const float2 b1 = sbuf[(q << 2) + 1];
    const float2 b2 = sbuf[(q << 2) + 2];
    const float2 b3 = sbuf[(q << 2) + 3];
    float4 o;
    o.x = a.x * b0.x + a.y * b0.y;
    o.y = a.x * b1.x + a.y * b1.y;
    o.z = a.x * b2.x + a.y * b2.y;
    o.w = a.x * b3.x + a.y * b3.y;
    out[(rr << 6) + q] = o;
}

// fallback for unexpected out_size (planar [Re|Im])
__global__ void __launch_bounds__(256)
outer_planar_kernel(float* __restrict__ out) {
    const int r = blockIdx.x;
    const int c = threadIdx.x;
    const float2 a = g_psi[r];
    const float2 b = g_psi[c];
    out[r * DIM + c]             = a.x * b.x + a.y * b.y;
    out[DIM * DIM + r * DIM + c] = a.y * b.x - a.x * b.y;
}

extern "C" void kernel_launch(void* const* d_in, const int* in_sizes, int n_in,
                              void* d_out, int out_size) {
    const float* x   = nullptr;
    const float* w   = nullptr;
    const float* cpl = nullptr;
    for (int i = 0; i < n_in; i++) {
        if      (in_sizes[i] == 256) x   = (const float*)d_in[i];
        else if (in_sizes[i] == 210) w   = (const float*)d_in[i];
        else if (in_sizes[i] == 64)  cpl = (const float*)d_in[i];
    }

    if (out_size == DIM * DIM) {
        fused_kernel<<<64, 256>>>(x, w, cpl, (float4*)d_out, 0);
    } else {
        fused_kernel<<<1, 256>>>(x, w, cpl, (float4*)d_out, 1);
        outer_planar_kernel<<<DIM, DIM>>>((float*)d_out);
    }
}